// round 5
// baseline (speedup 1.0000x reference)
#include <cuda_runtime.h>
#include <cstdint>

#define NBLK 128
#define TPB  512
#define T_STEPS 512
typedef unsigned long long ull;

// ---------------- persistent cross-layer spike buffers (batch-major [b][d]) --
__device__ float g_s0[2][128 * 1024];   // layer0 -> layer1 spikes
__device__ float g_s1[2][128 * 1024];   // layer1 -> layer2 spikes
__device__ unsigned g_arrive;
__device__ volatile unsigned g_epoch;

__global__ void snn_init_ctrl() { g_arrive = 0u; g_epoch = 0u; }

// ---------------- PTX helpers ----------------------------------------------
__device__ __forceinline__ void cpa4(uint32_t d, const float* s) {
    asm volatile("cp.async.ca.shared.global [%0], [%1], 4;" :: "r"(d), "l"(s));
}
// .cg (L2-only): spike buffers are written by other SMs and reuse addresses
// every 2 ticks -> must bypass per-SM L1.
__device__ __forceinline__ void cpa16(uint32_t d, const float* s) {
    asm volatile("cp.async.cg.shared.global [%0], [%1], 16;" :: "r"(d), "l"(s));
}
__device__ __forceinline__ void cp_commit() { asm volatile("cp.async.commit_group;"); }
template <int W> __device__ __forceinline__ void cp_wait() {
    asm volatile("cp.async.wait_group %0;" :: "n"(W));
}
// packed fp32x2 FMA: each half is an independent IEEE fp32 fma.rn -> the two
// lanes are bitwise identical to two scalar fmaf chains.
__device__ __forceinline__ void fma2(ull& d, ull a, ull b) {
    asm volatile("fma.rn.f32x2 %0, %1, %2, %0;" : "+l"(d) : "l"(a), "l"(b));
}
__device__ __forceinline__ ull packrr(float x) {   // splat (x, x)
    ull r;
    asm("mov.b64 %0, {%1, %2};" : "=l"(r) : "f"(x), "f"(x));
    return r;
}
__device__ __forceinline__ void unpack2(float& lo, float& hi, ull v) {
    asm("mov.b64 {%0, %1}, %2;" : "=f"(lo), "=f"(hi) : "l"(v));
}

// ---------------- software grid barrier (128 co-resident blocks) ------------
__device__ __forceinline__ void grid_barrier(unsigned target) {
    __syncthreads();
    if (threadIdx.x == 0) {
        __threadfence();                      // publish spike stores
        unsigned a = atomicAdd(&g_arrive, 1u);
        if (a == NBLK - 1u) {
            g_arrive = 0u;
            __threadfence();
            atomicExch((unsigned*)&g_epoch, target);
        } else {
            while (*((volatile unsigned*)&g_epoch) < target) __nanosleep(64);
            __threadfence();                  // acquire
        }
    }
    __syncthreads();
}

// ---------------- one 32x64 output tile of one layer at one timestep --------
// A in smem m-major As[m][k] (36-float padded rows, one LDS.128 = 4 k).
// B in smem k-major Bs[k][n] (LDS.64 = (b[n],b[n+1]) = ull, no pack needed).
// Accumulators are n-packed f32x2; per-output chain over k strictly ascending
// -> bitwise equal to the reference fp32 FMA chain.
__device__ __forceinline__ void run_tile(
    const float* __restrict__ Asrc,  // spike buffer [b][D], or raw inputs if gatherT >= 0
    int gatherT,                     // -1 => spike source; else timestep for input gather
    int Dsrc,                        // row stride of Asrc (1024 for spikes)
    const float* __restrict__ W, int K, int N,
    float (&mem)[4],                 // persistent membrane state (registers)
    float* __restrict__ spkOut,      // spike out [b][N-layer] (or null)
    float* __restrict__ outp,        // final output [128][512] (or null)
    int m0, int n0,
    float (*As)[36], float (*Bs)[64])   // smem: [3*32][36], [3*32][64]
{
    const int tid = threadIdx.x;
    // compute mapping: 16 warps = 8 m-warps x 2 n-warps; warp tile 4m x 32n;
    // thread tile 2m x 2n (rows mb, mb+1; cols nn, nn+1)
    const int w = tid >> 5, p = tid & 31;
    const int mb = (w >> 1) * 4 + (p >> 4) * 2;
    const int nn = (w & 1) * 32 + (p & 15) * 2;
    // loader mapping
    const int alm = tid >> 3, alq = tid & 7;      // A: threads 0..255 -> 32m x 8 quads
    const int blk = tid >> 4, blq = tid & 15;     // B: 512 threads -> 32k x 16 quads
    const int nch = K >> 5;
    const uint32_t aB = (uint32_t)__cvta_generic_to_shared(&As[0][0]);
    const uint32_t bB = (uint32_t)__cvta_generic_to_shared(&Bs[0][0]);

    auto load_chunk = [&](int st, int c) {
        const int k0 = c << 5;
        if (tid < 256) {
            uint32_t ad = aB + (uint32_t)(((st * 32 + alm) * 36 + alq * 4) * 4);
            if (gatherT >= 0) {
                // inputs[b][d][t]: As[m][k] = inputs[m0+m][k0+k][t]
                const float* gp = Asrc + (size_t)(m0 + alm) * (512 * 512)
                                       + (size_t)(k0 + alq * 4) * 512 + gatherT;
                cpa4(ad,       gp);
                cpa4(ad + 4u,  gp + 512);
                cpa4(ad + 8u,  gp + 1024);
                cpa4(ad + 12u, gp + 1536);
            } else {
                cpa16(ad, Asrc + (size_t)(m0 + alm) * Dsrc + k0 + alq * 4);
            }
        }
        uint32_t bd = bB + (uint32_t)(((st * 32 + blk) * 64 + blq * 4) * 4);
        cpa16(bd, W + (size_t)(k0 + blk) * N + n0 + blq * 4);
        cp_commit();
    };

    ull acc0 = 0ull, acc1 = 0ull;   // rows mb, mb+1; each = (nn, nn+1)

    load_chunk(0, 0);
    load_chunk(1, 1);
    cp_wait<1>();
    __syncthreads();

#pragma unroll 1
    for (int c = 0; c < nch; ++c) {
        const int st = c % 3;
        if (c + 2 < nch) load_chunk((c + 2) % 3, c + 2);
        const float* A_ = &As[st * 32][0];
        const float* B_ = &Bs[st * 32][0];
#pragma unroll
        for (int k4 = 0; k4 < 32; k4 += 4) {
            float4 a0 = *reinterpret_cast<const float4*>(A_ + (mb + 0) * 36 + k4);
            float4 a1 = *reinterpret_cast<const float4*>(A_ + (mb + 1) * 36 + k4);
            ull b;
            b = *reinterpret_cast<const ull*>(B_ + (k4 + 0) * 64 + nn);
            fma2(acc0, packrr(a0.x), b); fma2(acc1, packrr(a1.x), b);
            b = *reinterpret_cast<const ull*>(B_ + (k4 + 1) * 64 + nn);
            fma2(acc0, packrr(a0.y), b); fma2(acc1, packrr(a1.y), b);
            b = *reinterpret_cast<const ull*>(B_ + (k4 + 2) * 64 + nn);
            fma2(acc0, packrr(a0.z), b); fma2(acc1, packrr(a1.z), b);
            b = *reinterpret_cast<const ull*>(B_ + (k4 + 3) * 64 + nn);
            fma2(acc0, packrr(a0.w), b); fma2(acc1, packrr(a1.w), b);
        }
        if (c + 2 < nch) cp_wait<1>(); else cp_wait<0>();
        __syncthreads();
    }

    // epilogue: leaky integrate + reset-by-spike + fire (registers only)
    float cur[2][2];
    unpack2(cur[0][0], cur[0][1], acc0);
    unpack2(cur[1][0], cur[1][1], acc1);

    float s[2][2];
#pragma unroll
    for (int r = 0; r < 2; r++)
#pragma unroll
        for (int cc = 0; cc < 2; cc++) {
            float mv = mem[r * 2 + cc];
            float keep = (mv > 0.3f) ? 0.0f : 0.5f;      // prev spike derived from mem
            float mnew = fmaf(mv, keep, cur[r][cc]);     // mv*0.5 exact -> bitwise == ref
            mem[r * 2 + cc] = mnew;
            s[r][cc] = (mnew > 0.3f) ? 1.0f : 0.0f;
        }

    if (spkOut) {
#pragma unroll
        for (int r = 0; r < 2; r++)
            *reinterpret_cast<float2*>(spkOut + (size_t)(m0 + mb + r) * N + n0 + nn)
                = make_float2(s[r][0], s[r][1]);
    }
    if (outp) {
#pragma unroll
        for (int r = 0; r < 2; r++)
            *reinterpret_cast<float2*>(outp + (size_t)(m0 + mb + r) * 512 + n0 + nn)
                = make_float2(s[r][0], s[r][1]);
    }
}

// ---------------- persistent pipelined kernel --------------------------------
// Tick tau: L0 computes step tau, L1 step tau-1, L2 step tau-2 (independent).
// One grid barrier per tick; membrane state lives in registers for the whole run.
__global__ void __launch_bounds__(TPB, 1)
snn_kernel(const float* __restrict__ xin,
           const float* __restrict__ w0,
           const float* __restrict__ w1,
           const float* __restrict__ w2,
           float* __restrict__ out)
{
    __shared__ __align__(16) float As[3 * 32][36];
    __shared__ __align__(16) float Bs[3 * 32][64];
    const int bid = blockIdx.x;

    float memA[4], memB[4];
#pragma unroll
    for (int i = 0; i < 4; i++) { memA[i] = 0.0f; memB[i] = 0.0f; }

#pragma unroll 1
    for (int tick = 0; tick < T_STEPS + 2; ++tick) {
        if (bid < 64) {                       // layer 1: 4 x 16 tiles of 32x64
            const int t = tick - 1;
            if (t >= 0 && t < T_STEPS) {
                run_tile(g_s0[t & 1], -1, 1024, w1, 1024, 1024, memA,
                         g_s1[t & 1], nullptr,
                         (bid >> 4) * 32, (bid & 15) * 64, As, Bs);
            }
        } else if (bid < 96) {                // layer 2: 4 x 8 tiles
            const int t = tick - 2;
            if (t >= 0 && t < T_STEPS) {
                const int id = bid - 64;
                run_tile(g_s1[t & 1], -1, 1024, w2, 1024, 512, memA,
                         nullptr, (t == T_STEPS - 1) ? out : nullptr,
                         (id >> 3) * 32, (id & 7) * 64, As, Bs);
            }
        } else {                              // layer 0: two 32x64 tiles per block
            const int t = tick;
            if (t < T_STEPS) {
                const int i = bid - 96;
                {
                    const int id = 2 * i;
                    run_tile(xin, t, 0, w0, 512, 1024, memA, g_s0[t & 1], nullptr,
                             (id >> 4) * 32, (id & 15) * 64, As, Bs);
                }
                {
                    const int id = 2 * i + 1;
                    run_tile(xin, t, 0, w0, 512, 1024, memB, g_s0[t & 1], nullptr,
                             (id >> 4) * 32, (id & 15) * 64, As, Bs);
                }
            }
        }
        grid_barrier((unsigned)(tick + 1));
    }
}

extern "C" void kernel_launch(void* const* d_in, const int* in_sizes, int n_in,
                              void* d_out, int out_size)
{
    const float* xin = (const float*)d_in[0];   // inputs [128, 512, 512]
    const float* w0  = (const float*)d_in[1];   // [512, 1024]
    const float* w1  = (const float*)d_in[2];   // [1024, 1024]
    const float* w2  = (const float*)d_in[3];   // [1024, 512]
    float* out = (float*)d_out;                 // [128, 512]

    snn_init_ctrl<<<1, 1>>>();                  // reset barrier state every replay
    snn_kernel<<<NBLK, TPB>>>(xin, w0, w1, w2, out);
}

// round 6
// speedup vs baseline: 1.9691x; 1.9691x over previous
#include <cuda_runtime.h>
#include <cstdint>

#define NBLK 128
#define TPB  256
#define T_STEPS 512
#define KC 128
typedef unsigned long long ull;

// ---------------- persistent device state (no allocation) -------------------
__device__ float g_xT[512 * 128 * 512];   // inputs transposed: [t][b][d]
__device__ float g_s0[2][128 * 1024];     // layer0 -> layer1 spikes [b][d]
__device__ float g_s1[2][128 * 1024];     // layer1 -> layer2 spikes [b][d]
__device__ unsigned g_arrive;
__device__ volatile unsigned g_epoch;

__global__ void snn_init_ctrl() { g_arrive = 0u; g_epoch = 0u; }

// ---------------- PTX helpers ----------------------------------------------
// .cg (L2-only): spike buffers are written by other SMs and reuse addresses
// every 2 ticks -> must bypass per-SM L1. (xT/weights are read-only; .cg is
// harmless for them.)
__device__ __forceinline__ void cpa16(uint32_t d, const float* s) {
    asm volatile("cp.async.cg.shared.global [%0], [%1], 16;" :: "r"(d), "l"(s));
}
__device__ __forceinline__ void cp_commit() { asm volatile("cp.async.commit_group;"); }
template <int W> __device__ __forceinline__ void cp_wait() {
    asm volatile("cp.async.wait_group %0;" :: "n"(W));
}
// packed fp32x2 FMA: each lane is an independent IEEE fp32 fma.rn -> bitwise
// identical to two scalar fmaf chains.
__device__ __forceinline__ void fma2(ull& d, ull a, ull b) {
    asm volatile("fma.rn.f32x2 %0, %1, %2, %0;" : "+l"(d) : "l"(a), "l"(b));
}
__device__ __forceinline__ ull packrr(float x) {   // splat (x, x)
    ull r;
    asm("mov.b64 %0, {%1, %2};" : "=l"(r) : "f"(x), "f"(x));
    return r;
}
__device__ __forceinline__ void unpack2(float& lo, float& hi, ull v) {
    asm("mov.b64 {%0, %1}, %2;" : "=f"(lo), "=f"(hi) : "l"(v));
}

// ---------------- software grid barrier (128 co-resident blocks) ------------
__device__ __forceinline__ void grid_barrier(unsigned target) {
    __syncthreads();
    if (threadIdx.x == 0) {
        __threadfence();                      // publish spike stores
        unsigned a = atomicAdd(&g_arrive, 1u);
        if (a == NBLK - 1u) {
            g_arrive = 0u;
            __threadfence();
            atomicExch((unsigned*)&g_epoch, target);
        } else {
            while (*((volatile unsigned*)&g_epoch) < target) __nanosleep(64);
            __threadfence();                  // acquire
        }
    }
    __syncthreads();
}

// smem layout (dynamic): A[2][32][132] then B[2][128][64]
#define A_STRIDE 132
#define A_STAGE  (32 * A_STRIDE)        // 4224 floats
#define B_STAGE  (KC * 64)              // 8192 floats
#define SMEM_FLOATS (2 * A_STAGE + 2 * B_STAGE)   // 24832 floats = 99328 B

// ---------------- one 32x64 output tile of one layer at one timestep --------
// A m-major As[m][k] (132-float rows; LDS.128 = 4 k). B k-major Bs[k][n]
// (LDS.128 = 4 n = 2 f32x2 operands, zero pack cost). Accumulators n-packed
// f32x2; each output is one k-ascending fp32 FMA chain == reference bitwise.
__device__ __noinline__ void run_tile(
    const float* __restrict__ Asrc, int Dsrc,   // activation rows [b][Dsrc]
    const float* __restrict__ W, int K, int N,
    float* __restrict__ mem,                    // persistent membrane (8 regs)
    float* __restrict__ spkOut,                 // spike out [b][N] (or null)
    float* __restrict__ outp,                   // final output [128][512] (or null)
    int m0, int n0, float* sm)
{
    const int tid = threadIdx.x;
    // compute mapping: 8 warps = 4 m-warps x 2 n-warps; warp tile 8m x 32n;
    // thread tile 2m x 4n (rows mr, mr+1; cols cn..cn+3)
    const int w = tid >> 5, p = tid & 31;
    const int mr = (w >> 1) * 8 + (p >> 3) * 2;
    const int cn = (w & 1) * 32 + (p & 7) * 4;
    // loader mapping
    const int ar = tid >> 3, aq = tid & 7;      // A: 32 rows x 8 base-quads
    const int bk = tid >> 4, bq = tid & 15;     // B: 16 base-rows x 16 quads
    const int nch = K / KC;

    float* As = sm;
    float* Bs = sm + 2 * A_STAGE;
    const uint32_t aB = (uint32_t)__cvta_generic_to_shared(As);
    const uint32_t bB = (uint32_t)__cvta_generic_to_shared(Bs);

    auto load_chunk = [&](int st, int c) {
        const int k0 = c * KC;
        // A: 32 rows x 128 k  (4 quads per thread)
        const float* ap = Asrc + (size_t)(m0 + ar) * Dsrc + k0 + aq * 4;
        uint32_t ad = aB + (uint32_t)((st * A_STAGE + ar * A_STRIDE + aq * 4) * 4);
#pragma unroll
        for (int j = 0; j < 4; j++)
            cpa16(ad + (uint32_t)(j * 32 * 4), ap + j * 32);
        // B: 128 k-rows x 64 n  (8 quads per thread)
        const float* bp = W + (size_t)(k0 + bk) * N + n0 + bq * 4;
        uint32_t bd = bB + (uint32_t)((st * B_STAGE + bk * 64 + bq * 4) * 4);
#pragma unroll
        for (int j = 0; j < 8; j++)
            cpa16(bd + (uint32_t)(j * 16 * 64 * 4), bp + (size_t)(j * 16) * N);
        cp_commit();
    };

    ull acc00 = 0ull, acc01 = 0ull, acc10 = 0ull, acc11 = 0ull;

    load_chunk(0, 0);
#pragma unroll 1
    for (int c = 0; c < nch; ++c) {
        cp_wait<0>();          // buffer c landed (this thread's groups)
        __syncthreads();       // all threads' data visible; prev stage free
        if (c + 1 < nch) load_chunk((c + 1) & 1, c + 1);

        const float* A_ = As + (c & 1) * A_STAGE + mr * A_STRIDE;
        const float* B_ = Bs + (c & 1) * B_STAGE + cn;
#pragma unroll 8
        for (int k4 = 0; k4 < KC; k4 += 4) {
            float4 a0 = *reinterpret_cast<const float4*>(A_ + k4);
            float4 a1 = *reinterpret_cast<const float4*>(A_ + A_STRIDE + k4);
            ulonglong2 b0 = *reinterpret_cast<const ulonglong2*>(B_ + (k4 + 0) * 64);
            ulonglong2 b1 = *reinterpret_cast<const ulonglong2*>(B_ + (k4 + 1) * 64);
            ulonglong2 b2 = *reinterpret_cast<const ulonglong2*>(B_ + (k4 + 2) * 64);
            ulonglong2 b3 = *reinterpret_cast<const ulonglong2*>(B_ + (k4 + 3) * 64);
            ull s;
            s = packrr(a0.x); fma2(acc00, s, b0.x); fma2(acc01, s, b0.y);
            s = packrr(a1.x); fma2(acc10, s, b0.x); fma2(acc11, s, b0.y);
            s = packrr(a0.y); fma2(acc00, s, b1.x); fma2(acc01, s, b1.y);
            s = packrr(a1.y); fma2(acc10, s, b1.x); fma2(acc11, s, b1.y);
            s = packrr(a0.z); fma2(acc00, s, b2.x); fma2(acc01, s, b2.y);
            s = packrr(a1.z); fma2(acc10, s, b2.x); fma2(acc11, s, b2.y);
            s = packrr(a0.w); fma2(acc00, s, b3.x); fma2(acc01, s, b3.y);
            s = packrr(a1.w); fma2(acc10, s, b3.x); fma2(acc11, s, b3.y);
        }
    }

    // epilogue: leaky integrate + reset-by-spike + fire (registers only)
    float cur[2][4];
    unpack2(cur[0][0], cur[0][1], acc00);
    unpack2(cur[0][2], cur[0][3], acc01);
    unpack2(cur[1][0], cur[1][1], acc10);
    unpack2(cur[1][2], cur[1][3], acc11);

    float s[2][4];
#pragma unroll
    for (int r = 0; r < 2; r++)
#pragma unroll
        for (int cc = 0; cc < 4; cc++) {
            float mv = mem[r * 4 + cc];
            float keep = (mv > 0.3f) ? 0.0f : 0.5f;      // prev spike derived from mem
            float mnew = fmaf(mv, keep, cur[r][cc]);     // mv*0.5 exact -> bitwise == ref
            mem[r * 4 + cc] = mnew;
            s[r][cc] = (mnew > 0.3f) ? 1.0f : 0.0f;
        }

    if (spkOut) {
#pragma unroll
        for (int r = 0; r < 2; r++)
            *reinterpret_cast<float4*>(spkOut + (size_t)(m0 + mr + r) * N + cn + n0)
                = make_float4(s[r][0], s[r][1], s[r][2], s[r][3]);
    }
    if (outp) {
#pragma unroll
        for (int r = 0; r < 2; r++)
            *reinterpret_cast<float4*>(outp + (size_t)(m0 + mr + r) * 512 + cn + n0)
                = make_float4(s[r][0], s[r][1], s[r][2], s[r][3]);
    }
}

// ---------------- persistent pipelined kernel --------------------------------
// Phase 0: transpose inputs -> xT[t][b][d]. Then tick tau: L0 computes step
// tau, L1 step tau-1, L2 step tau-2. One grid barrier per tick; membrane
// state lives in registers for the whole run.
__global__ void __launch_bounds__(TPB, 1)
snn_kernel(const float* __restrict__ xin,
           const float* __restrict__ w0,
           const float* __restrict__ w1,
           const float* __restrict__ w2,
           float* __restrict__ out)
{
    extern __shared__ __align__(16) float sm[];
    const int bid = blockIdx.x;

    // ---- phase 0: transpose inputs [b][d][t] -> xT[t][b][d] (coalesced writes)
    {
        const int gtid = bid * TPB + threadIdx.x;
#pragma unroll 4
        for (int i = gtid; i < 512 * 128 * 512; i += NBLK * TPB) {
            const int t = i >> 16;
            const int bd = i & 65535;             // b*512 + d
            g_xT[i] = xin[(size_t)(bd >> 9) * 262144 + (size_t)(bd & 511) * 512 + t];
        }
    }
    grid_barrier(1u);

    float memA[8], memB[8];
#pragma unroll
    for (int i = 0; i < 8; i++) { memA[i] = 0.0f; memB[i] = 0.0f; }

#pragma unroll 1
    for (int tick = 0; tick < T_STEPS + 2; ++tick) {
        if (bid < 64) {                       // layer 1: 4 x 16 tiles of 32x64
            const int t = tick - 1;
            if (t >= 0 && t < T_STEPS) {
                run_tile(g_s0[t & 1], 1024, w1, 1024, 1024, memA,
                         g_s1[t & 1], nullptr,
                         (bid >> 4) * 32, (bid & 15) * 64, sm);
            }
        } else if (bid < 96) {                // layer 2: 4 x 8 tiles
            const int t = tick - 2;
            if (t >= 0 && t < T_STEPS) {
                const int id = bid - 64;
                run_tile(g_s1[t & 1], 1024, w2, 1024, 512, memA,
                         nullptr, (t == T_STEPS - 1) ? out : nullptr,
                         (id >> 3) * 32, (id & 7) * 64, sm);
            }
        } else {                              // layer 0: two 32x64 tiles per block
            const int t = tick;
            if (t < T_STEPS) {
                const int i = bid - 96;
                const float* xrow = g_xT + (size_t)t * 65536;
                {
                    const int id = 2 * i;
                    run_tile(xrow, 512, w0, 512, 1024, memA, g_s0[t & 1], nullptr,
                             (id >> 4) * 32, (id & 15) * 64, sm);
                }
                {
                    const int id = 2 * i + 1;
                    run_tile(xrow, 512, w0, 512, 1024, memB, g_s0[t & 1], nullptr,
                             (id >> 4) * 32, (id & 15) * 64, sm);
                }
            }
        }
        grid_barrier((unsigned)(tick + 2));
    }
}

extern "C" void kernel_launch(void* const* d_in, const int* in_sizes, int n_in,
                              void* d_out, int out_size)
{
    const float* xin = (const float*)d_in[0];   // inputs [128, 512, 512]
    const float* w0  = (const float*)d_in[1];   // [512, 1024]
    const float* w1  = (const float*)d_in[2];   // [1024, 1024]
    const float* w2  = (const float*)d_in[3];   // [1024, 512]
    float* out = (float*)d_out;                 // [128, 512]

    cudaFuncSetAttribute(snn_kernel, cudaFuncAttributeMaxDynamicSharedMemorySize,
                         SMEM_FLOATS * 4);
    snn_init_ctrl<<<1, 1>>>();                  // reset barrier state every replay
    snn_kernel<<<NBLK, TPB, SMEM_FLOATS * 4>>>(xin, w0, w1, w2, out);
}

// round 7
// speedup vs baseline: 2.0731x; 1.0528x over previous
#include <cuda_runtime.h>
#include <cstdint>

#define NBLK 128
#define TPB  256
#define T_STEPS 512
#define KC 128
#define DEPTH 4          // spike ring-buffer depth (pipeline slack)
typedef unsigned long long ull;

// ---------------- persistent device state (no allocation) -------------------
__device__ float g_xT[512 * 128 * 512];        // inputs transposed: [t][b][d]
__device__ float g_s0[DEPTH][128 * 1024];      // layer0 -> layer1 spikes [b][d]
__device__ float g_s1[DEPTH][128 * 1024];      // layer1 -> layer2 spikes [b][d]
// dataflow counters, one per 32-batch m-group: block-tick completions
__device__ unsigned g_cnt_l0[4];   // 8 L0 blocks per group per tick
__device__ unsigned g_cnt_l1[4];   // 16 L1 blocks per group per tick
__device__ unsigned g_cnt_l2[4];   // 8 L2 blocks per group per tick
__device__ unsigned g_arrive;      // one-time barrier after transpose
__device__ volatile unsigned g_epoch;

__global__ void snn_init_ctrl() {
    g_arrive = 0u; g_epoch = 0u;
    for (int i = 0; i < 4; i++) { g_cnt_l0[i] = 0u; g_cnt_l1[i] = 0u; g_cnt_l2[i] = 0u; }
}

// ---------------- PTX helpers ----------------------------------------------
// .cg (L2-only): spike buffers are written by other SMs and their ring slots
// are reused -> must bypass per-SM L1. Weights/xT have no L1 reuse anyway.
__device__ __forceinline__ void cpa16(uint32_t d, const float* s) {
    asm volatile("cp.async.cg.shared.global [%0], [%1], 16;" :: "r"(d), "l"(s));
}
__device__ __forceinline__ void cp_commit() { asm volatile("cp.async.commit_group;"); }
template <int W> __device__ __forceinline__ void cp_wait() {
    asm volatile("cp.async.wait_group %0;" :: "n"(W));
}
// packed fp32x2 FMA: each lane is an independent IEEE fp32 fma.rn -> bitwise
// identical to two scalar fmaf chains.
__device__ __forceinline__ void fma2(ull& d, ull a, ull b) {
    asm volatile("fma.rn.f32x2 %0, %1, %2, %0;" : "+l"(d) : "l"(a), "l"(b));
}
__device__ __forceinline__ ull packrr(float x) {   // splat (x, x)
    ull r;
    asm("mov.b64 %0, {%1, %2};" : "=l"(r) : "f"(x), "f"(x));
    return r;
}
__device__ __forceinline__ void unpack2(float& lo, float& hi, ull v) {
    asm("mov.b64 {%0, %1}, %2;" : "=f"(lo), "=f"(hi) : "l"(v));
}

// ---------------- dataflow sync ---------------------------------------------
// Consumer: block-wide wait until *cnt >= v (publishes via L2; producer did
// store -> __syncthreads -> __threadfence -> atomicAdd).
__device__ __forceinline__ void wait_ge(const unsigned* cnt, unsigned v) {
    __syncthreads();
    if (threadIdx.x == 0) {
        while (*((volatile const unsigned*)cnt) < v) __nanosleep(32);
        __threadfence();   // acquire before reading spike data
    }
    __syncthreads();
}
// Producer: all epilogue stores done -> publish one tick completion.
__device__ __forceinline__ void publish(unsigned* cnt) {
    __syncthreads();
    if (threadIdx.x == 0) { __threadfence(); atomicAdd(cnt, 1u); }
}

// ---------------- one-time grid barrier (after input transpose) -------------
__device__ __forceinline__ void grid_barrier(unsigned target) {
    __syncthreads();
    if (threadIdx.x == 0) {
        __threadfence();
        unsigned a = atomicAdd(&g_arrive, 1u);
        if (a == NBLK - 1u) {
            __threadfence();
            atomicExch((unsigned*)&g_epoch, target);
        } else {
            while (*((volatile unsigned*)&g_epoch) < target) __nanosleep(64);
            __threadfence();
        }
    }
    __syncthreads();
}

// smem layout (dynamic): A[3][32][132] then B[3][128][64]  (3-stage pipeline)
#define A_STRIDE 132
#define A_STAGE  (32 * A_STRIDE)        // 4224 floats
#define B_STAGE  (KC * 64)              // 8192 floats
#define SMEM_FLOATS (3 * A_STAGE + 3 * B_STAGE)   // 37248 floats = 148992 B

// ---------------- one 32x64 output tile of one layer at one timestep --------
// A m-major As[m][k] (132-float rows; LDS.128 = 4 k). B k-major Bs[k][n]
// (LDS.128 = 4 n = 2 f32x2 operands, zero pack cost). Accumulators n-packed
// f32x2; each output is one k-ascending fp32 FMA chain == reference bitwise.
__device__ __noinline__ void run_tile(
    const float* __restrict__ Asrc, int Dsrc,   // activation rows [b][Dsrc]
    const float* __restrict__ W, int K, int N,
    float* __restrict__ mem,                    // persistent membrane (8 regs)
    float* __restrict__ spkOut,                 // spike out [b][N] (or null)
    float* __restrict__ outp,                   // final output [128][512] (or null)
    int m0, int n0, float* sm)
{
    const int tid = threadIdx.x;
    // compute mapping: 8 warps = 4 m-warps x 2 n-warps; warp tile 8m x 32n;
    // thread tile 2m x 4n (rows mr, mr+1; cols cn..cn+3)
    const int w = tid >> 5, p = tid & 31;
    const int mr = (w >> 1) * 8 + (p >> 3) * 2;
    const int cn = (w & 1) * 32 + (p & 7) * 4;
    // loader mapping
    const int ar = tid >> 3, aq = tid & 7;      // A: 32 rows x 8 base-quads
    const int bk = tid >> 4, bq = tid & 15;     // B: 16 base-rows x 16 quads
    const int nch = K / KC;

    float* As = sm;
    float* Bs = sm + 3 * A_STAGE;
    const uint32_t aB = (uint32_t)__cvta_generic_to_shared(As);
    const uint32_t bB = (uint32_t)__cvta_generic_to_shared(Bs);

    auto load_chunk = [&](int st, int c) {
        const int k0 = c * KC;
        // A: 32 rows x 128 k  (4 quads per thread)
        const float* ap = Asrc + (size_t)(m0 + ar) * Dsrc + k0 + aq * 4;
        uint32_t ad = aB + (uint32_t)((st * A_STAGE + ar * A_STRIDE + aq * 4) * 4);
#pragma unroll
        for (int j = 0; j < 4; j++)
            cpa16(ad + (uint32_t)(j * 32 * 4), ap + j * 32);
        // B: 128 k-rows x 64 n  (8 quads per thread)
        const float* bp = W + (size_t)(k0 + bk) * N + n0 + bq * 4;
        uint32_t bd = bB + (uint32_t)((st * B_STAGE + bk * 64 + bq * 4) * 4);
#pragma unroll
        for (int j = 0; j < 8; j++)
            cpa16(bd + (uint32_t)(j * 16 * 64 * 4), bp + (size_t)(j * 16) * N);
        cp_commit();
    };

    ull acc00 = 0ull, acc01 = 0ull, acc10 = 0ull, acc11 = 0ull;

    load_chunk(0, 0);
    load_chunk(1, 1);
#pragma unroll 1
    for (int c = 0; c < nch; ++c) {
        cp_wait<1>();          // chunk c landed; chunk c+1 may stay in flight
        __syncthreads();       // all threads see it; stage (c+2)%3 is free
        if (c + 2 < nch) load_chunk((c + 2) % 3, c + 2);

        const float* A_ = As + (c % 3) * A_STAGE + mr * A_STRIDE;
        const float* B_ = Bs + (c % 3) * B_STAGE + cn;
#pragma unroll 8
        for (int k4 = 0; k4 < KC; k4 += 4) {
            float4 a0 = *reinterpret_cast<const float4*>(A_ + k4);
            float4 a1 = *reinterpret_cast<const float4*>(A_ + A_STRIDE + k4);
            ulonglong2 b0 = *reinterpret_cast<const ulonglong2*>(B_ + (k4 + 0) * 64);
            ulonglong2 b1 = *reinterpret_cast<const ulonglong2*>(B_ + (k4 + 1) * 64);
            ulonglong2 b2 = *reinterpret_cast<const ulonglong2*>(B_ + (k4 + 2) * 64);
            ulonglong2 b3 = *reinterpret_cast<const ulonglong2*>(B_ + (k4 + 3) * 64);
            ull s;
            s = packrr(a0.x); fma2(acc00, s, b0.x); fma2(acc01, s, b0.y);
            s = packrr(a1.x); fma2(acc10, s, b0.x); fma2(acc11, s, b0.y);
            s = packrr(a0.y); fma2(acc00, s, b1.x); fma2(acc01, s, b1.y);
            s = packrr(a1.y); fma2(acc10, s, b1.x); fma2(acc11, s, b1.y);
            s = packrr(a0.z); fma2(acc00, s, b2.x); fma2(acc01, s, b2.y);
            s = packrr(a1.z); fma2(acc10, s, b2.x); fma2(acc11, s, b2.y);
            s = packrr(a0.w); fma2(acc00, s, b3.x); fma2(acc01, s, b3.y);
            s = packrr(a1.w); fma2(acc10, s, b3.x); fma2(acc11, s, b3.y);
        }
    }

    // epilogue: leaky integrate + reset-by-spike + fire (registers only)
    float cur[2][4];
    unpack2(cur[0][0], cur[0][1], acc00);
    unpack2(cur[0][2], cur[0][3], acc01);
    unpack2(cur[1][0], cur[1][1], acc10);
    unpack2(cur[1][2], cur[1][3], acc11);

    float s[2][4];
#pragma unroll
    for (int r = 0; r < 2; r++)
#pragma unroll
        for (int cc = 0; cc < 4; cc++) {
            float mv = mem[r * 4 + cc];
            float keep = (mv > 0.3f) ? 0.0f : 0.5f;      // prev spike derived from mem
            float mnew = fmaf(mv, keep, cur[r][cc]);     // mv*0.5 exact -> bitwise == ref
            mem[r * 4 + cc] = mnew;
            s[r][cc] = (mnew > 0.3f) ? 1.0f : 0.0f;
        }

    if (spkOut) {
#pragma unroll
        for (int r = 0; r < 2; r++)
            *reinterpret_cast<float4*>(spkOut + (size_t)(m0 + mr + r) * N + cn + n0)
                = make_float4(s[r][0], s[r][1], s[r][2], s[r][3]);
    }
    if (outp) {
#pragma unroll
        for (int r = 0; r < 2; r++)
            *reinterpret_cast<float4*>(outp + (size_t)(m0 + mr + r) * 512 + cn + n0)
                = make_float4(s[r][0], s[r][1], s[r][2], s[r][3]);
    }
}

// ---------------- persistent dataflow kernel --------------------------------
// No per-tick grid barrier: each layer-block runs its own 512-step loop,
// ordered only by per-m-group producer/consumer counters with a DEPTH-4
// spike ring buffer. Membrane state lives in registers for the whole run.
__global__ void __launch_bounds__(TPB, 1)
snn_kernel(const float* __restrict__ xin,
           const float* __restrict__ w0,
           const float* __restrict__ w1,
           const float* __restrict__ w2,
           float* __restrict__ out)
{
    extern __shared__ __align__(16) float sm[];
    const int bid = blockIdx.x;

    // ---- phase 0: transpose inputs [b][d][t] -> xT[t][b][d] (coalesced writes)
    {
        const int gtid = bid * TPB + threadIdx.x;
#pragma unroll 4
        for (int i = gtid; i < 512 * 128 * 512; i += NBLK * TPB) {
            const int t = i >> 16;
            const int bd = i & 65535;             // b*512 + d
            g_xT[i] = xin[(size_t)(bd >> 9) * 262144 + (size_t)(bd & 511) * 512 + t];
        }
    }
    grid_barrier(1u);

    float memA[8], memB[8];
#pragma unroll
    for (int i = 0; i < 8; i++) { memA[i] = 0.0f; memB[i] = 0.0f; }

    if (bid < 64) {
        // ---- layer 1: 64 blocks; group g = bid>>4; tile 32x64
        const int g = bid >> 4;
        const int m0 = g * 32, n0 = (bid & 15) * 64;
#pragma unroll 1
        for (int t = 0; t < T_STEPS; ++t) {
            wait_ge(&g_cnt_l0[g], (unsigned)(8 * (t + 1)));          // s0[t] ready
            if (t >= DEPTH)
                wait_ge(&g_cnt_l2[g], (unsigned)(8 * (t - DEPTH + 1)));  // s1 slot free
            run_tile(g_s0[t & (DEPTH - 1)], 1024, w1, 1024, 1024, memA,
                     g_s1[t & (DEPTH - 1)], nullptr, m0, n0, sm);
            publish(&g_cnt_l1[g]);
        }
    } else if (bid < 96) {
        // ---- layer 2: 32 blocks; group g = (bid-64)>>3; tile 32x64
        const int id = bid - 64;
        const int g = id >> 3;
        const int m0 = g * 32, n0 = (id & 7) * 64;
#pragma unroll 1
        for (int t = 0; t < T_STEPS; ++t) {
            wait_ge(&g_cnt_l1[g], (unsigned)(16 * (t + 1)));         // s1[t] ready
            run_tile(g_s1[t & (DEPTH - 1)], 1024, w2, 1024, 512, memA,
                     nullptr, (t == T_STEPS - 1) ? out : nullptr, m0, n0, sm);
            publish(&g_cnt_l2[g]);
        }
    } else {
        // ---- layer 0: 32 blocks x 2 tiles; group g = id>>4 (same for both tiles)
        const int i = bid - 96;
        const int id0 = 2 * i, id1 = 2 * i + 1;
        const int g = id0 >> 4;
        const int mA = (id0 >> 4) * 32, nA = (id0 & 15) * 64;
        const int mB = (id1 >> 4) * 32, nB = (id1 & 15) * 64;
#pragma unroll 1
        for (int t = 0; t < T_STEPS; ++t) {
            if (t >= DEPTH)
                wait_ge(&g_cnt_l1[g], (unsigned)(16 * (t - DEPTH + 1)));  // s0 slot free
            const float* xrow = g_xT + (size_t)t * 65536;
            run_tile(xrow, 512, w0, 512, 1024, memA,
                     g_s0[t & (DEPTH - 1)], nullptr, mA, nA, sm);
            run_tile(xrow, 512, w0, 512, 1024, memB,
                     g_s0[t & (DEPTH - 1)], nullptr, mB, nB, sm);
            publish(&g_cnt_l0[g]);
        }
    }
}

extern "C" void kernel_launch(void* const* d_in, const int* in_sizes, int n_in,
                              void* d_out, int out_size)
{
    const float* xin = (const float*)d_in[0];   // inputs [128, 512, 512]
    const float* w0  = (const float*)d_in[1];   // [512, 1024]
    const float* w1  = (const float*)d_in[2];   // [1024, 1024]
    const float* w2  = (const float*)d_in[3];   // [1024, 512]
    float* out = (float*)d_out;                 // [128, 512]

    cudaFuncSetAttribute(snn_kernel, cudaFuncAttributeMaxDynamicSharedMemorySize,
                         SMEM_FLOATS * 4);
    snn_init_ctrl<<<1, 1>>>();                  // reset counters every replay
    snn_kernel<<<NBLK, TPB, SMEM_FLOATS * 4>>>(xin, w0, w1, w2, out);
}

// round 10
// speedup vs baseline: 2.0997x; 1.0128x over previous
#include <cuda_runtime.h>
#include <cstdint>

#define NBLK 128
#define TPB  256
#define T_STEPS 512
#define KC 128
#define DEPTH 4          // spike ring-buffer depth (pipeline slack)
typedef unsigned long long ull;

// ---------------- persistent device state (no allocation) -------------------
__device__ float g_xT[512 * 128 * 512];        // inputs transposed: [t][b][d]
__device__ float g_s0[DEPTH][128 * 1024];      // layer0 -> layer1 spikes [b][d]
__device__ float g_s1[DEPTH][128 * 1024];      // layer1 -> layer2 spikes [b][d]
// dataflow counters, one per 32-batch m-group: block-tick completions
__device__ unsigned g_cnt_l0[4];   // 8 L0 blocks per group per tick
__device__ unsigned g_cnt_l1[4];   // 16 L1 blocks per group per tick
__device__ unsigned g_cnt_l2[4];   // 8 L2 blocks per group per tick
__device__ unsigned g_arrive;      // one-time barrier after transpose
__device__ volatile unsigned g_epoch;

__global__ void snn_init_ctrl() {
    g_arrive = 0u; g_epoch = 0u;
    for (int i = 0; i < 4; i++) { g_cnt_l0[i] = 0u; g_cnt_l1[i] = 0u; g_cnt_l2[i] = 0u; }
}

// ---------------- PTX helpers ----------------------------------------------
// .cg (L2-only): spike buffers are written by other SMs and their ring slots
// are reused -> must bypass per-SM L1.
__device__ __forceinline__ void cpa16(uint32_t d, const float* s) {
    asm volatile("cp.async.cg.shared.global [%0], [%1], 16;" :: "r"(d), "l"(s));
}
__device__ __forceinline__ void cp_commit() { asm volatile("cp.async.commit_group;"); }
template <int W> __device__ __forceinline__ void cp_wait() {
    asm volatile("cp.async.wait_group %0;" :: "n"(W));
}
// packed fp32x2 FMA: each lane is an independent IEEE fp32 fma.rn -> bitwise
// identical to two scalar fmaf chains.
__device__ __forceinline__ void fma2(ull& d, ull a, ull b) {
    asm volatile("fma.rn.f32x2 %0, %1, %2, %0;" : "+l"(d) : "l"(a), "l"(b));
}
__device__ __forceinline__ ull packrr(float x) {   // splat (x, x)
    ull r;
    asm("mov.b64 %0, {%1, %2};" : "=l"(r) : "f"(x), "f"(x));
    return r;
}
__device__ __forceinline__ void unpack2(float& lo, float& hi, ull v) {
    asm("mov.b64 {%0, %1}, %2;" : "=f"(lo), "=f"(hi) : "l"(v));
}

// ---------------- dataflow sync ---------------------------------------------
__device__ __forceinline__ void wait_ge(const unsigned* cnt, unsigned v) {
    __syncthreads();
    if (threadIdx.x == 0) {
        while (*((volatile const unsigned*)cnt) < v) __nanosleep(32);
        __threadfence();   // acquire before reading spike data
    }
    __syncthreads();
}
__device__ __forceinline__ void publish(unsigned* cnt) {
    __syncthreads();
    if (threadIdx.x == 0) { __threadfence(); atomicAdd(cnt, 1u); }
}

// ---------------- one-time grid barrier (after transpose + B preload) -------
__device__ __forceinline__ void grid_barrier(unsigned target) {
    __syncthreads();
    if (threadIdx.x == 0) {
        __threadfence();
        unsigned a = atomicAdd(&g_arrive, 1u);
        if (a == NBLK - 1u) {
            __threadfence();
            atomicExch((unsigned*)&g_epoch, target);
        } else {
            while (*((volatile unsigned*)&g_epoch) < target) __nanosleep(64);
            __threadfence();
        }
    }
    __syncthreads();
}

// smem layout (dynamic floats):
//   Bres[4][128][64]  resident weight chunks (loaded once)   32768 floats
//   Bstr[2][128][64]  streamed weight stages                 16384 floats
//   Astg[2][32][132]  activation stages                       8448 floats
#define A_STRIDE 132
#define A_STAGE  (32 * A_STRIDE)
#define B_STAGE  (KC * 64)
#define SMEM_FLOATS (4 * B_STAGE + 2 * B_STAGE + 2 * A_STAGE)   // 57600 -> 230400 B

// ---------------- one 32x64 output tile of one layer at one timestep --------
// A m-major Astg[m][k] (132-float rows; LDS.128 = 4 k). B k-major [k][n]
// (LDS.128 = 4 n = 2 f32x2 operands). Inner loop register-double-buffers the
// next 4-k fragment while FMAing the current one. Each output is one
// k-ascending fp32 FMA chain == reference bitwise.
__device__ __noinline__ void run_tile(
    const float* __restrict__ Asrc, int Dsrc,   // activation rows [b][Dsrc]
    const float* __restrict__ Wg, int K, int N, // global weights
    const float* __restrict__ Bres, int nres,   // smem resident B chunks
    float* __restrict__ Bstr, float* __restrict__ Astg,
    float* __restrict__ mem,                    // persistent membrane (8 regs)
    float* __restrict__ spkOut,                 // spike out [b][N] (or null)
    float* __restrict__ outp,                   // final output [128][512] (or null)
    int m0, int n0)
{
    const int tid = threadIdx.x;
    const int w = tid >> 5, p = tid & 31;
    const int mr = (w >> 1) * 8 + (p >> 3) * 2;      // 2 m-rows
    const int cn = (w & 1) * 32 + (p & 7) * 4;       // 4 n-cols
    const int ar = tid >> 3, aq = tid & 7;           // A loader
    const int bk = tid >> 4, bq = tid & 15;          // B loader
    const int nch = K / KC;
    const uint32_t aB = (uint32_t)__cvta_generic_to_shared(Astg);
    const uint32_t bB = (uint32_t)__cvta_generic_to_shared(Bstr);

    auto loadA = [&](int st, int c) {
        const float* ap = Asrc + (size_t)(m0 + ar) * Dsrc + c * KC + aq * 4;
        uint32_t ad = aB + (uint32_t)((st * A_STAGE + ar * A_STRIDE + aq * 4) * 4);
#pragma unroll
        for (int j = 0; j < 4; j++)
            cpa16(ad + (uint32_t)(j * 32 * 4), ap + j * 32);
    };
    auto loadB = [&](int st, int c) {
        const float* bp = Wg + (size_t)(c * KC + bk) * N + n0 + bq * 4;
        uint32_t bd = bB + (uint32_t)((st * B_STAGE + bk * 64 + bq * 4) * 4);
#pragma unroll
        for (int j = 0; j < 8; j++)
            cpa16(bd + (uint32_t)(j * 16 * 64 * 4), bp + (size_t)(j * 16) * N);
    };

    ull acc00 = 0ull, acc01 = 0ull, acc10 = 0ull, acc11 = 0ull;

    loadA(0, 0);              // chunk 0: B resident, only A streams
    cp_commit();

#pragma unroll 1
    for (int c = 0; c < nch; ++c) {
        cp_wait<0>();
        __syncthreads();
        if (c + 1 < nch) {
            loadA((c + 1) & 1, c + 1);
            if (c + 1 >= nres) loadB((c + 1 - nres) & 1, c + 1);
            cp_commit();
        }
        const float* A_ = Astg + (c & 1) * A_STAGE + mr * A_STRIDE;
        const float* Ar1 = A_ + A_STRIDE;
        const float* B_ = ((c < nres) ? (Bres + c * B_STAGE)
                                      : (Bstr + ((c - nres) & 1) * B_STAGE)) + cn;

        // register double-buffered inner loop (prefetch k4+4 while FMAing k4)
        float4 ca0 = *reinterpret_cast<const float4*>(A_);
        float4 ca1 = *reinterpret_cast<const float4*>(Ar1);
        ulonglong2 cb0 = *reinterpret_cast<const ulonglong2*>(B_ + 0 * 64);
        ulonglong2 cb1 = *reinterpret_cast<const ulonglong2*>(B_ + 1 * 64);
        ulonglong2 cb2 = *reinterpret_cast<const ulonglong2*>(B_ + 2 * 64);
        ulonglong2 cb3 = *reinterpret_cast<const ulonglong2*>(B_ + 3 * 64);
#pragma unroll
        for (int k4 = 0; k4 < KC; k4 += 4) {
            float4 na0 = ca0, na1 = ca1;
            ulonglong2 nb0 = cb0, nb1 = cb1, nb2 = cb2, nb3 = cb3;
            if (k4 + 4 < KC) {
                na0 = *reinterpret_cast<const float4*>(A_ + k4 + 4);
                na1 = *reinterpret_cast<const float4*>(Ar1 + k4 + 4);
                nb0 = *reinterpret_cast<const ulonglong2*>(B_ + (k4 + 4) * 64);
                nb1 = *reinterpret_cast<const ulonglong2*>(B_ + (k4 + 5) * 64);
                nb2 = *reinterpret_cast<const ulonglong2*>(B_ + (k4 + 6) * 64);
                nb3 = *reinterpret_cast<const ulonglong2*>(B_ + (k4 + 7) * 64);
            }
            ull s;
            s = packrr(ca0.x); fma2(acc00, s, cb0.x); fma2(acc01, s, cb0.y);
            s = packrr(ca1.x); fma2(acc10, s, cb0.x); fma2(acc11, s, cb0.y);
            s = packrr(ca0.y); fma2(acc00, s, cb1.x); fma2(acc01, s, cb1.y);
            s = packrr(ca1.y); fma2(acc10, s, cb1.x); fma2(acc11, s, cb1.y);
            s = packrr(ca0.z); fma2(acc00, s, cb2.x); fma2(acc01, s, cb2.y);
            s = packrr(ca1.z); fma2(acc10, s, cb2.x); fma2(acc11, s, cb2.y);
            s = packrr(ca0.w); fma2(acc00, s, cb3.x); fma2(acc01, s, cb3.y);
            s = packrr(ca1.w); fma2(acc10, s, cb3.x); fma2(acc11, s, cb3.y);
            ca0 = na0; ca1 = na1; cb0 = nb0; cb1 = nb1; cb2 = nb2; cb3 = nb3;
        }
    }

    // epilogue: leaky integrate + reset-by-spike + fire (registers only)
    float cur[2][4];
    unpack2(cur[0][0], cur[0][1], acc00);
    unpack2(cur[0][2], cur[0][3], acc01);
    unpack2(cur[1][0], cur[1][1], acc10);
    unpack2(cur[1][2], cur[1][3], acc11);

    float s[2][4];
#pragma unroll
    for (int r = 0; r < 2; r++)
#pragma unroll
        for (int cc = 0; cc < 4; cc++) {
            float mv = mem[r * 4 + cc];
            float keep = (mv > 0.3f) ? 0.0f : 0.5f;      // prev spike derived from mem
            float mnew = fmaf(mv, keep, cur[r][cc]);     // mv*0.5 exact -> bitwise == ref
            mem[r * 4 + cc] = mnew;
            s[r][cc] = (mnew > 0.3f) ? 1.0f : 0.0f;
        }

    if (spkOut) {
#pragma unroll
        for (int r = 0; r < 2; r++)
            *reinterpret_cast<float4*>(spkOut + (size_t)(m0 + mr + r) * N + cn + n0)
                = make_float4(s[r][0], s[r][1], s[r][2], s[r][3]);
    }
    if (outp) {
#pragma unroll
        for (int r = 0; r < 2; r++)
            *reinterpret_cast<float4*>(outp + (size_t)(m0 + mr + r) * 512 + cn + n0)
                = make_float4(s[r][0], s[r][1], s[r][2], s[r][3]);
    }
}

// ---------------- persistent dataflow kernel --------------------------------
__global__ void __launch_bounds__(TPB, 1)
snn_kernel(const float* __restrict__ xin,
           const float* __restrict__ w0,
           const float* __restrict__ w1,
           const float* __restrict__ w2,
           float* __restrict__ out)
{
    extern __shared__ __align__(16) float sm[];
    float* Bres = sm;                        // 4 resident B chunks
    float* Bstr = sm + 4 * B_STAGE;          // 2 streamed B stages
    float* Astg = sm + 6 * B_STAGE;          // 2 A stages
    const int bid = blockIdx.x;
    const int tid = threadIdx.x;
    const int bk = tid >> 4, bq = tid & 15;
    const uint32_t brB = (uint32_t)__cvta_generic_to_shared(Bres);

    // resident-B preload helper (slot s <- weight chunk c of (Wg, N, n0))
    auto preB = [&](int slot, const float* Wg, int N, int n0, int c) {
        const float* bp = Wg + (size_t)(c * KC + bk) * N + n0 + bq * 4;
        uint32_t bd = brB + (uint32_t)((slot * B_STAGE + bk * 64 + bq * 4) * 4);
#pragma unroll
        for (int j = 0; j < 8; j++)
            cpa16(bd + (uint32_t)(j * 16 * 64 * 4), bp + (size_t)(j * 16) * N);
    };

    // ---- phase 0: issue resident-B loads, then transpose inputs ------------
    if (bid < 64) {
        const int n0 = (bid & 15) * 64;
        for (int c = 0; c < 4; c++) preB(c, w1, 1024, n0, c);
    } else if (bid < 96) {
        const int id = bid - 64;
        const int n0 = (id & 7) * 64;
        for (int c = 0; c < 4; c++) preB(c, w2, 512, n0, c);
    } else {
        const int i = bid - 96;
        const int nA = ((2 * i) & 15) * 64, nB = ((2 * i + 1) & 15) * 64;
        preB(0, w0, 1024, nA, 0); preB(1, w0, 1024, nA, 1);
        preB(2, w0, 1024, nB, 0); preB(3, w0, 1024, nB, 1);
    }
    cp_commit();

    {   // transpose inputs [b][d][t] -> xT[t][b][d] (coalesced writes)
        const int gtid = bid * TPB + tid;
#pragma unroll 4
        for (int i = gtid; i < 512 * 128 * 512; i += NBLK * TPB) {
            const int t = i >> 16;
            const int bd = i & 65535;             // b*512 + d
            g_xT[i] = xin[(size_t)(bd >> 9) * 262144 + (size_t)(bd & 511) * 512 + t];
        }
    }
    cp_wait<0>();          // resident B landed
    grid_barrier(1u);

    float memA[8], memB[8];
#pragma unroll
    for (int i = 0; i < 8; i++) { memA[i] = 0.0f; memB[i] = 0.0f; }

    if (bid < 64) {
        // ---- layer 1: 64 blocks; group g = bid>>4; tile 32x64
        const int g = bid >> 4;
        const int m0 = g * 32, n0 = (bid & 15) * 64;
#pragma unroll 1
        for (int t = 0; t < T_STEPS; ++t) {
            wait_ge(&g_cnt_l0[g], (unsigned)(8 * (t + 1)));              // s0[t] ready
            if (t >= DEPTH)
                wait_ge(&g_cnt_l2[g], (unsigned)(8 * (t - DEPTH + 1)));  // s1 slot free
            run_tile(g_s0[t & (DEPTH - 1)], 1024, w1, 1024, 1024,
                     Bres, 4, Bstr, Astg, memA,
                     g_s1[t & (DEPTH - 1)], nullptr, m0, n0);
            publish(&g_cnt_l1[g]);
        }
    } else if (bid < 96) {
        // ---- layer 2: 32 blocks; group g = (bid-64)>>3; tile 32x64
        const int id = bid - 64;
        const int g = id >> 3;
        const int m0 = g * 32, n0 = (id & 7) * 64;
#pragma unroll 1
        for (int t = 0; t < T_STEPS; ++t) {
            wait_ge(&g_cnt_l1[g], (unsigned)(16 * (t + 1)));             // s1[t] ready
            run_tile(g_s1[t & (DEPTH - 1)], 1024, w2, 1024, 512,
                     Bres, 4, Bstr, Astg, memA,
                     nullptr, (t == T_STEPS - 1) ? out : nullptr, m0, n0);
            publish(&g_cnt_l2[g]);
        }
    } else {
        // ---- layer 0: 32 blocks x 2 tiles; K=512 (4 chunks, 2 resident each)
        const int i = bid - 96;
        const int id0 = 2 * i, id1 = 2 * i + 1;
        const int g = id0 >> 4;
        const int mA = (id0 >> 4) * 32, nA = (id0 & 15) * 64;
        const int mB = (id1 >> 4) * 32, nB = (id1 & 15) * 64;
#pragma unroll 1
        for (int t = 0; t < T_STEPS; ++t) {
            if (t >= DEPTH)
                wait_ge(&g_cnt_l1[g], (unsigned)(16 * (t - DEPTH + 1)));  // s0 slot free
            const float* xrow = g_xT + (size_t)t * 65536;
            run_tile(xrow, 512, w0, 512, 1024,
                     Bres, 2, Bstr, Astg, memA,
                     g_s0[t & (DEPTH - 1)], nullptr, mA, nA);
            run_tile(xrow, 512, w0, 512, 1024,
                     Bres + 2 * B_STAGE, 2, Bstr, Astg, memB,
                     g_s0[t & (DEPTH - 1)], nullptr, mB, nB);
            publish(&g_cnt_l0[g]);
        }
    }
}

extern "C" void kernel_launch(void* const* d_in, const int* in_sizes, int n_in,
                              void* d_out, int out_size)
{
    const float* xin = (const float*)d_in[0];   // inputs [128, 512, 512]
    const float* w0  = (const float*)d_in[1];   // [512, 1024]
    const float* w1  = (const float*)d_in[2];   // [1024, 1024]
    const float* w2  = (const float*)d_in[3];   // [1024, 512]
    float* out = (float*)d_out;                 // [128, 512]

    static bool attr_set = false;
    if (!attr_set) {
        cudaFuncSetAttribute(snn_kernel, cudaFuncAttributeMaxDynamicSharedMemorySize,
                             SMEM_FLOATS * 4);
        attr_set = true;   // idempotent config, not a call-count guard on work
    }
    snn_init_ctrl<<<1, 1>>>();                  // reset counters every replay
    snn_kernel<<<NBLK, TPB, SMEM_FLOATS * 4>>>(xin, w0, w1, w2, out);
}